// round 15
// baseline (speedup 1.0000x reference)
#include <cuda_runtime.h>
#include <cuda_fp16.h>
#include <math.h>

#define LSEQ 4096
#define HDIM 2048
#define HKN  16
#define HVN  32
#define KEY_DIM  2048
#define VAL_DIM  4096
#define CONV_DIM 8192
#define NPROJ    12352
#define QKVZ_DIM 12288
#define EPSF 1e-6f

// ---------------- scratch (device globals; no runtime allocation) ------------
__device__ float g_proj [LSEQ * (size_t)NPROJ];
__device__ float g_mixed[LSEQ * (size_t)CONV_DIM];   // only v region used
__device__ float g_qn   [LSEQ * (size_t)KEY_DIM];
__device__ float g_kn   [LSEQ * (size_t)KEY_DIM];
__device__ float g_g    [LSEQ * HVN];
__device__ float g_beta [LSEQ * HVN];
__device__ float g_core [LSEQ * (size_t)VAL_DIM];

// fp16 buffers
__device__ __half g_hs_h [LSEQ * (size_t)HDIM];
__device__ __half g_win_h[(size_t)HDIM * NPROJ];
__device__ __half g_win_l[(size_t)HDIM * NPROJ];
__device__ __half g_wout_h[(size_t)VAL_DIM * HDIM];
__device__ __half g_y_h [LSEQ * (size_t)VAL_DIM];

// ---------------- helpers ----------------------------------------------------
__device__ __forceinline__ unsigned sptr(const void* p) {
    return (unsigned)__cvta_generic_to_shared(p);
}
__device__ __forceinline__ void ldsm4(unsigned &r0, unsigned &r1, unsigned &r2, unsigned &r3, unsigned a) {
    asm volatile("ldmatrix.sync.aligned.m8n8.x4.shared.b16 {%0,%1,%2,%3},[%4];"
                 : "=r"(r0), "=r"(r1), "=r"(r2), "=r"(r3) : "r"(a));
}
__device__ __forceinline__ void ldsm4t(unsigned &r0, unsigned &r1, unsigned &r2, unsigned &r3, unsigned a) {
    asm volatile("ldmatrix.sync.aligned.m8n8.x4.trans.shared.b16 {%0,%1,%2,%3},[%4];"
                 : "=r"(r0), "=r"(r1), "=r"(r2), "=r"(r3) : "r"(a));
}
__device__ __forceinline__ void mma_f16(float* c, const unsigned* a, const unsigned* b) {
    asm volatile("mma.sync.aligned.m16n8k16.row.col.f32.f16.f16.f32 "
                 "{%0,%1,%2,%3},{%4,%5,%6,%7},{%8,%9},{%0,%1,%2,%3};"
                 : "+f"(c[0]), "+f"(c[1]), "+f"(c[2]), "+f"(c[3])
                 : "r"(a[0]), "r"(a[1]), "r"(a[2]), "r"(a[3]), "r"(b[0]), "r"(b[1]));
}
__device__ __forceinline__ void cpa16(unsigned d, const void* s, int sz) {
    asm volatile("cp.async.cg.shared.global [%0],[%1],16,%2;" :: "r"(d), "l"(s), "r"(sz));
}
// 128-thread sum reduction: intra-warp shfl + 4-value smem exchange (2 barriers)
__device__ __forceinline__ float block128_sum(float v, float* s4, int tid) {
    v += __shfl_xor_sync(0xffffffffu, v, 16);
    v += __shfl_xor_sync(0xffffffffu, v, 8);
    v += __shfl_xor_sync(0xffffffffu, v, 4);
    v += __shfl_xor_sync(0xffffffffu, v, 2);
    v += __shfl_xor_sync(0xffffffffu, v, 1);
    if ((tid & 31) == 0) s4[tid >> 5] = v;
    __syncthreads();
    float r = (s4[0] + s4[1]) + (s4[2] + s4[3]);
    return r;
}

// ---------------- fp32 -> fp16 (round only) -----------------------------------
__global__ void cvt16_kernel(const float4* __restrict__ x,
                             __half* __restrict__ h, int n4)
{
    int i = blockIdx.x * blockDim.x + threadIdx.x;
    if (i >= n4) return;
    float4 v = x[i];
    __half2* o = (__half2*)h;
    o[2*i]   = __floats2half2_rn(v.x, v.y);
    o[2*i+1] = __floats2half2_rn(v.z, v.w);
}

// ---------------- fp32 -> (fp16 hi, fp16 lo) exact split ----------------------
__global__ void split16_kernel(const float4* __restrict__ x,
                               __half* __restrict__ hi,
                               __half* __restrict__ lo, int n4)
{
    int i = blockIdx.x * blockDim.x + threadIdx.x;
    if (i >= n4) return;
    float4 v = x[i];
    float f[4] = {v.x, v.y, v.z, v.w};
    __half h[4], l[4];
#pragma unroll
    for (int j = 0; j < 4; j++) {
        h[j] = __float2half(f[j]);
        l[j] = __float2half(f[j] - __half2float(h[j]));
    }
    ((__half2*)hi)[2*i]   = __halves2half2(h[0], h[1]);
    ((__half2*)hi)[2*i+1] = __halves2half2(h[2], h[3]);
    ((__half2*)lo)[2*i]   = __halves2half2(l[0], l[1]);
    ((__half2*)lo)[2*i+1] = __halves2half2(l[2], l[3]);
}

// ---------------- GEMM tile config --------------------------------------------
#define BM 128
#define BN 128
#define BK 64
#define A_ST 72
#define B_ST 136
#define A_TILE (BM * A_ST)
#define B_TILE (BK * B_ST)
#define GEMM2P_SMEM ((2 * A_TILE + 4 * B_TILE) * 2)   // 106496 B
#define GEMM1P_SMEM ((2 * A_TILE + 2 * B_TILE) * 2)   // 71680 B

// ---------------- fp16 2-pass GEMM: C = A @ (Bh+Bl) ---------------------------
__global__ __launch_bounds__(256, 2) void hgemm2(
    const __half* __restrict__ Ah,
    const __half* __restrict__ Bh, const __half* __restrict__ Bl,
    float* __restrict__ C, int M, int N, int K)
{
    extern __shared__ __half sm[];
    __half* sA  = sm;
    __half* sBh = sm + 2 * A_TILE;
    __half* sBl = sm + 2 * A_TILE + 2 * B_TILE;

    const int tid  = threadIdx.x;
    const int lane = tid & 31;
    const int wid  = tid >> 5;
    const int wm   = (wid & 1) * 64;
    const int wn   = (wid >> 1) * 32;

    const int rowBase = blockIdx.y * BM;
    const int colBase = blockIdx.x * BN;

    float acc[4][4][4];
#pragma unroll
    for (int a = 0; a < 4; a++)
#pragma unroll
        for (int b = 0; b < 4; b++)
#pragma unroll
            for (int c = 0; c < 4; c++) acc[a][b][c] = 0.f;

    const int numTiles = K / BK;

    auto issue_tile = [&](int t, int buf) {
        const int k0 = t * BK;
#pragma unroll
        for (int i = 0; i < 4; i++) {
            int c  = tid + i * 256;
            int r  = c >> 3;
            int kc = (c & 7) * 8;
            size_t goff = (size_t)(rowBase + r) * K + k0 + kc;
            cpa16(sptr(sA + buf * A_TILE + r * A_ST + kc), Ah + goff, 16);
        }
#pragma unroll
        for (int i = 0; i < 4; i++) {
            int c  = tid + i * 256;
            int r  = c >> 4;
            int nc = (c & 15) * 8;
            int col = colBase + nc;
            int sz  = (col < N) ? 16 : 0;
            size_t goff = sz ? ((size_t)(k0 + r) * N + col) : 0;
            int soff = buf * B_TILE + r * B_ST + nc;
            cpa16(sptr(sBh + soff), Bh + goff, sz);
            cpa16(sptr(sBl + soff), Bl + goff, sz);
        }
        asm volatile("cp.async.commit_group;");
    };

    issue_tile(0, 0);

    int buf = 0;
    for (int t = 0; t < numTiles; t++) {
        if (t + 1 < numTiles) issue_tile(t + 1, buf ^ 1);
        else                  asm volatile("cp.async.commit_group;");
        asm volatile("cp.async.wait_group 1;");
        __syncthreads();

        const __half* pA  = sA  + buf * A_TILE;
        const __half* pBh = sBh + buf * B_TILE;
        const __half* pBl = sBl + buf * B_TILE;

#pragma unroll
        for (int ks = 0; ks < 4; ks++) {
            unsigned ah[4][4], bh[4][2], bl[4][2];
            const int ar = lane & 15;
            const int ac = ks * 16 + (lane >> 4) * 8;
#pragma unroll
            for (int mt = 0; mt < 4; mt++) {
                unsigned ad = sptr(pA + (wm + mt * 16 + ar) * A_ST + ac);
                ldsm4(ah[mt][0], ah[mt][1], ah[mt][2], ah[mt][3], ad);
            }
            const int brow = ks * 16 + (lane & 7) + ((lane & 8) ? 8 : 0);
            const int bcsel = ((lane >> 4) & 1) * 8;
#pragma unroll
            for (int pr = 0; pr < 2; pr++) {
                int bc = wn + pr * 16 + bcsel;
                unsigned bd = sptr(pBh + brow * B_ST + bc);
                ldsm4t(bh[pr*2][0], bh[pr*2][1], bh[pr*2+1][0], bh[pr*2+1][1], bd);
                unsigned bd2 = sptr(pBl + brow * B_ST + bc);
                ldsm4t(bl[pr*2][0], bl[pr*2][1], bl[pr*2+1][0], bl[pr*2+1][1], bd2);
            }
#pragma unroll
            for (int mt = 0; mt < 4; mt++)
#pragma unroll
                for (int nt = 0; nt < 4; nt++) {
                    mma_f16(acc[mt][nt], ah[mt], bh[nt]);
                    mma_f16(acc[mt][nt], ah[mt], bl[nt]);
                }
        }
        __syncthreads();
        buf ^= 1;
    }

#pragma unroll
    for (int mt = 0; mt < 4; mt++)
#pragma unroll
        for (int nt = 0; nt < 4; nt++) {
            int row = rowBase + wm + mt * 16 + (lane >> 2);
            int col = colBase + wn + nt * 8 + (lane & 3) * 2;
            if (col < N) {
                float2 v0 = make_float2(acc[mt][nt][0], acc[mt][nt][1]);
                float2 v1 = make_float2(acc[mt][nt][2], acc[mt][nt][3]);
                *(float2*)(C + (size_t)row * N + col)       = v0;
                *(float2*)(C + (size_t)(row + 8) * N + col) = v1;
            }
        }
}

// ---------------- fp16 1-pass GEMM: C = A @ B (out_proj) ----------------------
__global__ __launch_bounds__(256, 2) void hgemm1(
    const __half* __restrict__ Ah, const __half* __restrict__ Bh,
    float* __restrict__ C, int M, int N, int K)
{
    extern __shared__ __half sm[];
    __half* sA  = sm;
    __half* sBh = sm + 2 * A_TILE;

    const int tid  = threadIdx.x;
    const int lane = tid & 31;
    const int wid  = tid >> 5;
    const int wm   = (wid & 1) * 64;
    const int wn   = (wid >> 1) * 32;

    const int rowBase = blockIdx.y * BM;
    const int colBase = blockIdx.x * BN;

    float acc[4][4][4];
#pragma unroll
    for (int a = 0; a < 4; a++)
#pragma unroll
        for (int b = 0; b < 4; b++)
#pragma unroll
            for (int c = 0; c < 4; c++) acc[a][b][c] = 0.f;

    const int numTiles = K / BK;

    auto issue_tile = [&](int t, int buf) {
        const int k0 = t * BK;
#pragma unroll
        for (int i = 0; i < 4; i++) {
            int c  = tid + i * 256;
            int r  = c >> 3;
            int kc = (c & 7) * 8;
            size_t goff = (size_t)(rowBase + r) * K + k0 + kc;
            cpa16(sptr(sA + buf * A_TILE + r * A_ST + kc), Ah + goff, 16);
        }
#pragma unroll
        for (int i = 0; i < 4; i++) {
            int c  = tid + i * 256;
            int r  = c >> 4;
            int nc = (c & 15) * 8;
            int col = colBase + nc;
            int sz  = (col < N) ? 16 : 0;
            size_t goff = sz ? ((size_t)(k0 + r) * N + col) : 0;
            cpa16(sptr(sBh + buf * B_TILE + r * B_ST + nc), Bh + goff, sz);
        }
        asm volatile("cp.async.commit_group;");
    };

    issue_tile(0, 0);

    int buf = 0;
    for (int t = 0; t < numTiles; t++) {
        if (t + 1 < numTiles) issue_tile(t + 1, buf ^ 1);
        else                  asm volatile("cp.async.commit_group;");
        asm volatile("cp.async.wait_group 1;");
        __syncthreads();

        const __half* pA  = sA  + buf * A_TILE;
        const __half* pBh = sBh + buf * B_TILE;

#pragma unroll
        for (int ks = 0; ks < 4; ks++) {
            unsigned ah[4][4], bh[4][2];
            const int ar = lane & 15;
            const int ac = ks * 16 + (lane >> 4) * 8;
#pragma unroll
            for (int mt = 0; mt < 4; mt++) {
                unsigned ad = sptr(pA + (wm + mt * 16 + ar) * A_ST + ac);
                ldsm4(ah[mt][0], ah[mt][1], ah[mt][2], ah[mt][3], ad);
            }
            const int brow = ks * 16 + (lane & 7) + ((lane & 8) ? 8 : 0);
            const int bcsel = ((lane >> 4) & 1) * 8;
#pragma unroll
            for (int pr = 0; pr < 2; pr++) {
                int bc = wn + pr * 16 + bcsel;
                unsigned bd = sptr(pBh + brow * B_ST + bc);
                ldsm4t(bh[pr*2][0], bh[pr*2][1], bh[pr*2+1][0], bh[pr*2+1][1], bd);
            }
#pragma unroll
            for (int mt = 0; mt < 4; mt++)
#pragma unroll
                for (int nt = 0; nt < 4; nt++)
                    mma_f16(acc[mt][nt], ah[mt], bh[nt]);
        }
        __syncthreads();
        buf ^= 1;
    }

#pragma unroll
    for (int mt = 0; mt < 4; mt++)
#pragma unroll
        for (int nt = 0; nt < 4; nt++) {
            int row = rowBase + wm + mt * 16 + (lane >> 2);
            int col = colBase + wn + nt * 8 + (lane & 3) * 2;
            if (col < N) {
                float2 v0 = make_float2(acc[mt][nt][0], acc[mt][nt][1]);
                float2 v1 = make_float2(acc[mt][nt][2], acc[mt][nt][3]);
                *(float2*)(C + (size_t)row * N + col)       = v0;
                *(float2*)(C + (size_t)(row + 8) * N + col) = v1;
            }
        }
}

// ---------------- fused conv(K=4) + SiLU + L2norm for q/k ---------------------
__global__ __launch_bounds__(128) void conv_qk_kernel(const float* __restrict__ conv_w)
{
    const int t = blockIdx.x;
    const int h = blockIdx.y;
    const int d = threadIdx.x;
    const bool isQ = h < HKN;
    const int hk = isQ ? h : h - HKN;

    const int c   = (isQ ? 0 : KEY_DIM) + hk * 128 + d;
    const int col = hk * 768 + (isQ ? 0 : 128) + d;

    float accv = 0.f;
#pragma unroll
    for (int j = 0; j < 4; j++) {
        const int tt = t - 3 + j;
        if (tt >= 0)
            accv = fmaf(conv_w[c * 4 + j], g_proj[(size_t)tt * NPROJ + col], accv);
    }
    const float v = accv / (1.f + expf(-accv));

    __shared__ float s4[4];
    const float ss = block128_sum(v * v, s4, d);

    float scale = 1.f / sqrtf(ss + EPSF);
    if (isQ) scale *= 0.08838834764831845f;
    const float outv = v * scale;
    if (isQ) g_qn[(size_t)t * KEY_DIM + hk * 128 + d] = outv;
    else     g_kn[(size_t)t * KEY_DIM + hk * 128 + d] = outv;
}

// ---------------- conv(K=4) + SiLU for v (float4 vectorized) ------------------
__global__ void conv_v_kernel(const float* __restrict__ conv_w)
{
    const int i = blockIdx.x * blockDim.x + threadIdx.x;
    if (i >= LSEQ * VAL_DIM / 4) return;
    const int t  = i >> 10;
    const int c4 = (i & 1023) * 4;
    const int col = (c4 >> 8) * 768 + 256 + (c4 & 255);

    const float4 w0 = ((const float4*)conv_w)[VAL_DIM + c4 + 0];
    const float4 w1 = ((const float4*)conv_w)[VAL_DIM + c4 + 1];
    const float4 w2 = ((const float4*)conv_w)[VAL_DIM + c4 + 2];
    const float4 w3 = ((const float4*)conv_w)[VAL_DIM + c4 + 3];

    float4 a = make_float4(0.f, 0.f, 0.f, 0.f);
#pragma unroll
    for (int j = 0; j < 4; j++) {
        const int tt = t - 3 + j;
        if (tt >= 0) {
            const float4 x = *(const float4*)&g_proj[(size_t)tt * NPROJ + col];
            a.x = fmaf(((const float*)&w0)[j], x.x, a.x);
            a.y = fmaf(((const float*)&w1)[j], x.y, a.y);
            a.z = fmaf(((const float*)&w2)[j], x.z, a.z);
            a.w = fmaf(((const float*)&w3)[j], x.w, a.w);
        }
    }
    float4 o;
    o.x = a.x / (1.f + expf(-a.x));
    o.y = a.y / (1.f + expf(-a.y));
    o.z = a.z / (1.f + expf(-a.z));
    o.w = a.w / (1.f + expf(-a.w));
    *(float4*)&g_mixed[(size_t)t * CONV_DIM + 2 * KEY_DIM + c4] = o;
}

// ---------------- beta / g activations ---------------------------------------
__global__ void gb_kernel(const float* __restrict__ A_log,
                          const float* __restrict__ dt_bias)
{
    const int i = blockIdx.x * blockDim.x + threadIdx.x;
    if (i >= LSEQ * HVN) return;
    const int t  = i >> 5;
    const int hv = i & 31;
    const int hk = hv >> 1;
    const int gi = hv & 1;
    const float* row = g_proj + (size_t)t * NPROJ + QKVZ_DIM + hk * 4;
    const float b = row[gi];
    const float a = row[2 + gi];
    g_beta[i] = 1.f / (1.f + expf(-b));
    const float x  = a + dt_bias[hv];
    const float sp = (x > 20.f) ? x : log1pf(expf(x));
    g_g[i] = -expf(A_log[hv]) * sp;
}

// ---------------- gated delta recurrence (256 threads, 8 sub-rows) ------------
// Block = (hv, colgroup of 32 cols). Thread: col j = tid>>3, sub-row r = tid&7,
// owning S rows [r*16, r*16+16). Reduction over 8 consecutive lanes (shfl 1,2,4).
// skq padded: row -> row + (row>>4)  => bank (2r+2i) mod 32, conflict-free.
__global__ __launch_bounds__(256, 1) void scan_kernel3()
{
    const int hv = blockIdx.x >> 2;
    const int cg = blockIdx.x & 3;
    const int tid = threadIdx.x;
    const int j  = tid >> 3;          // 0..31 column within group
    const int r  = tid & 7;           // 0..7 sub-row (16 rows each)
    const int col = cg * 32 + j;
    const int hk = hv >> 1;

    float S[16];
#pragma unroll
    for (int i = 0; i < 16; i++) S[i] = 0.f;

    __shared__ float2 skq[2][136];    // 128 rows padded: idx = row + (row>>4)

    const float* kb = g_kn + hk * 128;
    const float* qb = g_qn + hk * 128;
    const float* vb = g_mixed + 2 * KEY_DIM + hv * 128 + col;
    const int sidx = (tid < 128) ? (tid + (tid >> 4)) : 0;

    float2 kq = make_float2(0.f, 0.f);
    if (tid < 128) kq = make_float2(kb[tid], qb[tid]);
    float vv = vb[0];
    float gg = g_g[hv];
    float bb = g_beta[hv];
    if (tid < 128) skq[0][sidx] = kq;
    __syncthreads();

    const int rbase = r * 17;         // contiguous padded range for rows r*16..+15

    for (int t = 0; t < LSEQ; t++) {
        const int buf = t & 1;
        float2 kq_n = make_float2(0.f, 0.f);
        float vv_n = 0.f, gg_n = 0.f, bb_n = 0.f;
        if (t + 1 < LSEQ) {
            if (tid < 128)
                kq_n = make_float2(kb[(size_t)(t + 1) * KEY_DIM + tid],
                                   qb[(size_t)(t + 1) * KEY_DIM + tid]);
            vv_n = vb[(size_t)(t + 1) * CONV_DIM];
            gg_n = g_g[(t + 1) * HVN + hv];
            bb_n = g_beta[(t + 1) * HVN + hv];
        }

        const float eg = expf(gg);
        const float2* kqrow = &skq[buf][rbase];

        float k0 = 0.f, k1 = 0.f, k2 = 0.f, k3 = 0.f;
#pragma unroll
        for (int i = 0; i < 16; i += 4) {
            S[i + 0] *= eg; k0 = fmaf(kqrow[i + 0].x, S[i + 0], k0);
            S[i + 1] *= eg; k1 = fmaf(kqrow[i + 1].x, S[i + 1], k1);
            S[i + 2] *= eg; k2 = fmaf(kqrow[i + 2].x, S[i + 2], k2);
            S[i + 3] *= eg; k3 = fmaf(kqrow[i + 3].x, S[i + 3], k3);
        }
        float ks = (k0 + k1) + (k2 + k3);
        ks += __shfl_xor_sync(0xffffffffu, ks, 1);
        ks += __shfl_xor_sync(0xffffffffu, ks, 2);
        ks += __shfl_xor_sync(0xffffffffu, ks, 4);
        const float delta = (vv - ks) * bb;

        float o0 = 0.f, o1 = 0.f, o2 = 0.f, o3 = 0.f;
#pragma unroll
        for (int i = 0; i < 16; i += 4) {
            float2 a0 = kqrow[i + 0]; S[i + 0] = fmaf(a0.x, delta, S[i + 0]); o0 = fmaf(a0.y, S[i + 0], o0);
            float2 a1 = kqrow[i + 1]; S[i + 1] = fmaf(a1.x, delta, S[i + 1]); o1 = fmaf(a1.y, S[i + 1], o1);
            float2 a2 = kqrow[i + 2]; S[i + 2] = fmaf(a2.x, delta, S[i + 2]); o2 = fmaf(a2.y, S[i + 2], o2);
            float2 a3 = kqrow[i + 3]; S[i + 3] = fmaf(a3.x, delta, S[i + 3]); o3 = fmaf(a3.y, S[i + 3], o3);
        }
        float o = (o0 + o1) + (o2 + o3);
        o += __shfl_xor_sync(0xffffffffu, o, 1);
        o += __shfl_xor_sync(0xffffffffu, o, 2);
        o += __shfl_xor_sync(0xffffffffu, o, 4);
        if (r == 0)
            g_core[(size_t)t * VAL_DIM + hv * 128 + col] = o;

        if (t + 1 < LSEQ) {
            if (tid < 128) skq[buf ^ 1][sidx] = kq_n;
            vv = vv_n; gg = gg_n; bb = bb_n;
        }
        __syncthreads();
    }
}

// ---------------- gated RMSNorm * silu(z), writes fp16 y ----------------------
__global__ __launch_bounds__(128) void gated_norm_kernel(const float* __restrict__ norm_w)
{
    const int t  = blockIdx.x;
    const int hv = blockIdx.y;
    const int d  = threadIdx.x;
    const int hk = hv >> 1;
    const int gi = hv & 1;

    const float c = g_core[(size_t)t * VAL_DIM + hv * 128 + d];

    __shared__ float s4[4];
    const float ss = block128_sum(c * c, s4, d);
    const float var = ss * (1.f / 128.f);

    const float z  = g_proj[(size_t)t * NPROJ + hk * 768 + 512 + gi * 128 + d];
    const float sz = z / (1.f + expf(-z));

    const float yv = c * (1.f / sqrtf(var + EPSF)) * norm_w[d] * sz;
    g_y_h[(size_t)t * VAL_DIM + hv * 128 + d] = __float2half(yv);
}

// ---------------- launch ------------------------------------------------------
extern "C" void kernel_launch(void* const* d_in, const int* in_sizes, int n_in,
                              void* d_out, int out_size)
{
    const float* hs      = (const float*)d_in[0];
    const float* w_in    = (const float*)d_in[1];
    const float* conv_w  = (const float*)d_in[2];
    const float* A_log   = (const float*)d_in[3];
    const float* dt_bias = (const float*)d_in[4];
    const float* norm_w  = (const float*)d_in[5];
    const float* w_out   = (const float*)d_in[6];
    float* out = (float*)d_out;

    static bool init = false;
    static cudaStream_t s_aux;
    static cudaEvent_t ev0, ev1, ev2, ev3;
    if (!init) {
        cudaFuncSetAttribute(hgemm2,
                             cudaFuncAttributeMaxDynamicSharedMemorySize, GEMM2P_SMEM);
        cudaFuncSetAttribute(hgemm1,
                             cudaFuncAttributeMaxDynamicSharedMemorySize, GEMM1P_SMEM);
        cudaStreamCreateWithFlags(&s_aux, cudaStreamNonBlocking);
        cudaEventCreateWithFlags(&ev0, cudaEventDisableTiming);
        cudaEventCreateWithFlags(&ev1, cudaEventDisableTiming);
        cudaEventCreateWithFlags(&ev2, cudaEventDisableTiming);
        cudaEventCreateWithFlags(&ev3, cudaEventDisableTiming);
        init = true;
    }

    float *proj_p = nullptr;
    __half *hs_h, *win_h, *win_l, *wout_h, *y_h;
    cudaGetSymbolAddress((void**)&proj_p, g_proj);
    cudaGetSymbolAddress((void**)&hs_h,   g_hs_h);
    cudaGetSymbolAddress((void**)&win_h,  g_win_h);
    cudaGetSymbolAddress((void**)&win_l,  g_win_l);
    cudaGetSymbolAddress((void**)&wout_h, g_wout_h);
    cudaGetSymbolAddress((void**)&y_h,    g_y_h);

    // Fork: wout cvt runs on aux stream, overlapping split + GEMM1.
    cudaEventRecord(ev0, 0);
    cudaStreamWaitEvent(s_aux, ev0, 0);
    {
        int n4 = VAL_DIM * HDIM / 4;
        cvt16_kernel<<<(n4 + 255) / 256, 256, 0, s_aux>>>(
            (const float4*)w_out, wout_h, n4);
    }
    cudaEventRecord(ev1, s_aux);

    // Main stream: activation cvt + weight split + in_proj GEMM.
    {
        int n4 = LSEQ * HDIM / 4;
        cvt16_kernel<<<(n4 + 255) / 256, 256>>>((const float4*)hs, hs_h, n4);
        n4 = HDIM * NPROJ / 4;
        split16_kernel<<<(n4 + 255) / 256, 256>>>((const float4*)w_in, win_h, win_l, n4);
    }
    hgemm2<<<dim3((NPROJ + BN - 1) / BN, LSEQ / BM), 256, GEMM2P_SMEM>>>(
        hs_h, win_h, win_l, proj_p, LSEQ, NPROJ, HDIM);

    // Fork: conv_v + gb on aux stream, overlapping conv_qk.
    cudaEventRecord(ev2, 0);
    cudaStreamWaitEvent(s_aux, ev2, 0);
    conv_v_kernel<<<(LSEQ * VAL_DIM / 4 + 255) / 256, 256, 0, s_aux>>>(conv_w);
    gb_kernel<<<(LSEQ * HVN + 255) / 256, 256, 0, s_aux>>>(A_log, dt_bias);
    cudaEventRecord(ev3, s_aux);

    conv_qk_kernel<<<dim3(LSEQ, 32), 128>>>(conv_w);

    // Join: scan needs conv_qk (main), conv_v + gb (aux).
    cudaStreamWaitEvent(0, ev3, 0);
    scan_kernel3<<<HVN * 4, 256>>>();

    gated_norm_kernel<<<dim3(LSEQ, HVN), 128>>>(norm_w);

    // Join: out_proj needs wout_h from aux stream.
    cudaStreamWaitEvent(0, ev1, 0);
    hgemm1<<<dim3(HDIM / BN, LSEQ / BM), 256, GEMM1P_SMEM>>>(
        y_h, wout_h, out, LSEQ, HDIM, VAL_DIM);
}

// round 16
// speedup vs baseline: 1.3918x; 1.3918x over previous
#include <cuda_runtime.h>
#include <cuda_fp16.h>
#include <math.h>

#define LSEQ 4096
#define HDIM 2048
#define HKN  16
#define HVN  32
#define KEY_DIM  2048
#define VAL_DIM  4096
#define CONV_DIM 8192
#define NPROJ    12352
#define QKVZ_DIM 12288
#define EPSF 1e-6f

// ---------------- scratch (device globals; no runtime allocation) ------------
__device__ float g_proj [LSEQ * (size_t)NPROJ];
__device__ float g_mixed[LSEQ * (size_t)CONV_DIM];   // only v region used
__device__ float g_qn   [LSEQ * (size_t)KEY_DIM];
__device__ float g_kn   [LSEQ * (size_t)KEY_DIM];
__device__ float g_g    [LSEQ * HVN];
__device__ float g_beta [LSEQ * HVN];
__device__ float g_core [LSEQ * (size_t)VAL_DIM];

// fp16 buffers (all operands 1-pass fp16 now)
__device__ __half g_hs_h [LSEQ * (size_t)HDIM];
__device__ __half g_win_h[(size_t)HDIM * NPROJ];
__device__ __half g_wout_h[(size_t)VAL_DIM * HDIM];
__device__ __half g_y_h [LSEQ * (size_t)VAL_DIM];

// ---------------- helpers ----------------------------------------------------
__device__ __forceinline__ unsigned sptr(const void* p) {
    return (unsigned)__cvta_generic_to_shared(p);
}
__device__ __forceinline__ void ldsm4(unsigned &r0, unsigned &r1, unsigned &r2, unsigned &r3, unsigned a) {
    asm volatile("ldmatrix.sync.aligned.m8n8.x4.shared.b16 {%0,%1,%2,%3},[%4];"
                 : "=r"(r0), "=r"(r1), "=r"(r2), "=r"(r3) : "r"(a));
}
__device__ __forceinline__ void ldsm4t(unsigned &r0, unsigned &r1, unsigned &r2, unsigned &r3, unsigned a) {
    asm volatile("ldmatrix.sync.aligned.m8n8.x4.trans.shared.b16 {%0,%1,%2,%3},[%4];"
                 : "=r"(r0), "=r"(r1), "=r"(r2), "=r"(r3) : "r"(a));
}
__device__ __forceinline__ void mma_f16(float* c, const unsigned* a, const unsigned* b) {
    asm volatile("mma.sync.aligned.m16n8k16.row.col.f32.f16.f16.f32 "
                 "{%0,%1,%2,%3},{%4,%5,%6,%7},{%8,%9},{%0,%1,%2,%3};"
                 : "+f"(c[0]), "+f"(c[1]), "+f"(c[2]), "+f"(c[3])
                 : "r"(a[0]), "r"(a[1]), "r"(a[2]), "r"(a[3]), "r"(b[0]), "r"(b[1]));
}
__device__ __forceinline__ void cpa16(unsigned d, const void* s, int sz) {
    asm volatile("cp.async.cg.shared.global [%0],[%1],16,%2;" :: "r"(d), "l"(s), "r"(sz));
}
// 128-thread sum reduction: intra-warp shfl + 4-value smem exchange (2 barriers)
__device__ __forceinline__ float block128_sum(float v, float* s4, int tid) {
    v += __shfl_xor_sync(0xffffffffu, v, 16);
    v += __shfl_xor_sync(0xffffffffu, v, 8);
    v += __shfl_xor_sync(0xffffffffu, v, 4);
    v += __shfl_xor_sync(0xffffffffu, v, 2);
    v += __shfl_xor_sync(0xffffffffu, v, 1);
    if ((tid & 31) == 0) s4[tid >> 5] = v;
    __syncthreads();
    float r = (s4[0] + s4[1]) + (s4[2] + s4[3]);
    return r;
}

// ---------------- fp32 -> fp16 (round only) -----------------------------------
__global__ void cvt16_kernel(const float4* __restrict__ x,
                             __half* __restrict__ h, int n4)
{
    int i = blockIdx.x * blockDim.x + threadIdx.x;
    if (i >= n4) return;
    float4 v = x[i];
    __half2* o = (__half2*)h;
    o[2*i]   = __floats2half2_rn(v.x, v.y);
    o[2*i+1] = __floats2half2_rn(v.z, v.w);
}

// ---------------- GEMM tile config --------------------------------------------
#define BM 128
#define BN 128
#define BK 64
#define A_ST 72
#define B_ST 136
#define A_TILE (BM * A_ST)
#define B_TILE (BK * B_ST)
#define GEMM1P_SMEM ((2 * A_TILE + 2 * B_TILE) * 2)   // 71680 B

// ---------------- fp16 1-pass GEMM: C = A @ B ---------------------------------
__global__ __launch_bounds__(256, 2) void hgemm1(
    const __half* __restrict__ Ah, const __half* __restrict__ Bh,
    float* __restrict__ C, int M, int N, int K)
{
    extern __shared__ __half sm[];
    __half* sA  = sm;
    __half* sBh = sm + 2 * A_TILE;

    const int tid  = threadIdx.x;
    const int lane = tid & 31;
    const int wid  = tid >> 5;
    const int wm   = (wid & 1) * 64;
    const int wn   = (wid >> 1) * 32;

    const int rowBase = blockIdx.y * BM;
    const int colBase = blockIdx.x * BN;

    float acc[4][4][4];
#pragma unroll
    for (int a = 0; a < 4; a++)
#pragma unroll
        for (int b = 0; b < 4; b++)
#pragma unroll
            for (int c = 0; c < 4; c++) acc[a][b][c] = 0.f;

    const int numTiles = K / BK;

    auto issue_tile = [&](int t, int buf) {
        const int k0 = t * BK;
#pragma unroll
        for (int i = 0; i < 4; i++) {
            int c  = tid + i * 256;
            int r  = c >> 3;
            int kc = (c & 7) * 8;
            size_t goff = (size_t)(rowBase + r) * K + k0 + kc;
            cpa16(sptr(sA + buf * A_TILE + r * A_ST + kc), Ah + goff, 16);
        }
#pragma unroll
        for (int i = 0; i < 4; i++) {
            int c  = tid + i * 256;
            int r  = c >> 4;
            int nc = (c & 15) * 8;
            int col = colBase + nc;
            int sz  = (col < N) ? 16 : 0;
            size_t goff = sz ? ((size_t)(k0 + r) * N + col) : 0;
            cpa16(sptr(sBh + buf * B_TILE + r * B_ST + nc), Bh + goff, sz);
        }
        asm volatile("cp.async.commit_group;");
    };

    issue_tile(0, 0);

    int buf = 0;
    for (int t = 0; t < numTiles; t++) {
        if (t + 1 < numTiles) issue_tile(t + 1, buf ^ 1);
        else                  asm volatile("cp.async.commit_group;");
        asm volatile("cp.async.wait_group 1;");
        __syncthreads();

        const __half* pA  = sA  + buf * A_TILE;
        const __half* pBh = sBh + buf * B_TILE;

#pragma unroll
        for (int ks = 0; ks < 4; ks++) {
            unsigned ah[4][4], bh[4][2];
            const int ar = lane & 15;
            const int ac = ks * 16 + (lane >> 4) * 8;
#pragma unroll
            for (int mt = 0; mt < 4; mt++) {
                unsigned ad = sptr(pA + (wm + mt * 16 + ar) * A_ST + ac);
                ldsm4(ah[mt][0], ah[mt][1], ah[mt][2], ah[mt][3], ad);
            }
            const int brow = ks * 16 + (lane & 7) + ((lane & 8) ? 8 : 0);
            const int bcsel = ((lane >> 4) & 1) * 8;
#pragma unroll
            for (int pr = 0; pr < 2; pr++) {
                int bc = wn + pr * 16 + bcsel;
                unsigned bd = sptr(pBh + brow * B_ST + bc);
                ldsm4t(bh[pr*2][0], bh[pr*2][1], bh[pr*2+1][0], bh[pr*2+1][1], bd);
            }
#pragma unroll
            for (int mt = 0; mt < 4; mt++)
#pragma unroll
                for (int nt = 0; nt < 4; nt++)
                    mma_f16(acc[mt][nt], ah[mt], bh[nt]);
        }
        __syncthreads();
        buf ^= 1;
    }

#pragma unroll
    for (int mt = 0; mt < 4; mt++)
#pragma unroll
        for (int nt = 0; nt < 4; nt++) {
            int row = rowBase + wm + mt * 16 + (lane >> 2);
            int col = colBase + wn + nt * 8 + (lane & 3) * 2;
            if (col < N) {
                float2 v0 = make_float2(acc[mt][nt][0], acc[mt][nt][1]);
                float2 v1 = make_float2(acc[mt][nt][2], acc[mt][nt][3]);
                *(float2*)(C + (size_t)row * N + col)       = v0;
                *(float2*)(C + (size_t)(row + 8) * N + col) = v1;
            }
        }
}

// ---------------- fused conv(K=4) + SiLU + L2norm for q/k ---------------------
__global__ __launch_bounds__(128) void conv_qk_kernel(const float* __restrict__ conv_w)
{
    const int t = blockIdx.x;
    const int h = blockIdx.y;
    const int d = threadIdx.x;
    const bool isQ = h < HKN;
    const int hk = isQ ? h : h - HKN;

    const int c   = (isQ ? 0 : KEY_DIM) + hk * 128 + d;
    const int col = hk * 768 + (isQ ? 0 : 128) + d;

    float accv = 0.f;
#pragma unroll
    for (int j = 0; j < 4; j++) {
        const int tt = t - 3 + j;
        if (tt >= 0)
            accv = fmaf(conv_w[c * 4 + j], g_proj[(size_t)tt * NPROJ + col], accv);
    }
    const float v = accv / (1.f + expf(-accv));

    __shared__ float s4[4];
    const float ss = block128_sum(v * v, s4, d);

    float scale = 1.f / sqrtf(ss + EPSF);
    if (isQ) scale *= 0.08838834764831845f;
    const float outv = v * scale;
    if (isQ) g_qn[(size_t)t * KEY_DIM + hk * 128 + d] = outv;
    else     g_kn[(size_t)t * KEY_DIM + hk * 128 + d] = outv;
}

// ---------------- conv(K=4) + SiLU for v (float4 vectorized) ------------------
__global__ void conv_v_kernel(const float* __restrict__ conv_w)
{
    const int i = blockIdx.x * blockDim.x + threadIdx.x;
    if (i >= LSEQ * VAL_DIM / 4) return;
    const int t  = i >> 10;
    const int c4 = (i & 1023) * 4;
    const int col = (c4 >> 8) * 768 + 256 + (c4 & 255);

    const float4 w0 = ((const float4*)conv_w)[VAL_DIM + c4 + 0];
    const float4 w1 = ((const float4*)conv_w)[VAL_DIM + c4 + 1];
    const float4 w2 = ((const float4*)conv_w)[VAL_DIM + c4 + 2];
    const float4 w3 = ((const float4*)conv_w)[VAL_DIM + c4 + 3];

    float4 a = make_float4(0.f, 0.f, 0.f, 0.f);
#pragma unroll
    for (int j = 0; j < 4; j++) {
        const int tt = t - 3 + j;
        if (tt >= 0) {
            const float4 x = *(const float4*)&g_proj[(size_t)tt * NPROJ + col];
            a.x = fmaf(((const float*)&w0)[j], x.x, a.x);
            a.y = fmaf(((const float*)&w1)[j], x.y, a.y);
            a.z = fmaf(((const float*)&w2)[j], x.z, a.z);
            a.w = fmaf(((const float*)&w3)[j], x.w, a.w);
        }
    }
    float4 o;
    o.x = a.x / (1.f + expf(-a.x));
    o.y = a.y / (1.f + expf(-a.y));
    o.z = a.z / (1.f + expf(-a.z));
    o.w = a.w / (1.f + expf(-a.w));
    *(float4*)&g_mixed[(size_t)t * CONV_DIM + 2 * KEY_DIM + c4] = o;
}

// ---------------- beta / g activations ---------------------------------------
__global__ void gb_kernel(const float* __restrict__ A_log,
                          const float* __restrict__ dt_bias)
{
    const int i = blockIdx.x * blockDim.x + threadIdx.x;
    if (i >= LSEQ * HVN) return;
    const int t  = i >> 5;
    const int hv = i & 31;
    const int hk = hv >> 1;
    const int gi = hv & 1;
    const float* row = g_proj + (size_t)t * NPROJ + QKVZ_DIM + hk * 4;
    const float b = row[gi];
    const float a = row[2 + gi];
    g_beta[i] = 1.f / (1.f + expf(-b));
    const float x  = a + dt_bias[hv];
    const float sp = (x > 20.f) ? x : log1pf(expf(x));
    g_g[i] = -expf(A_log[hv]) * sp;
}

// ---------------- gated delta recurrence (4-way split accumulators) ----------
__global__ __launch_bounds__(128, 1) void scan_kernel2()
{
    const int hv = blockIdx.x >> 2;
    const int cg = blockIdx.x & 3;
    const int tid = threadIdx.x;
    const int j  = tid >> 2;
    const int r  = tid & 3;
    const int col = cg * 32 + j;
    const int hk = hv >> 1;

    float S[32];
#pragma unroll
    for (int i = 0; i < 32; i++) S[i] = 0.f;

    __shared__ float2 skq[2][4 * 33];

    const float* kb = g_kn + hk * 128;
    const float* qb = g_qn + hk * 128;
    const float* vb = g_mixed + 2 * KEY_DIM + hv * 128 + col;
    const int sidx = (tid >> 5) * 33 + (tid & 31);

    float2 kq = make_float2(kb[tid], qb[tid]);
    float vv = vb[0];
    float gg = g_g[hv];
    float bb = g_beta[hv];
    skq[0][sidx] = kq;
    __syncthreads();

    for (int t = 0; t < LSEQ; t++) {
        const int buf = t & 1;
        float2 kq_n; float vv_n = 0.f, gg_n = 0.f, bb_n = 0.f;
        if (t + 1 < LSEQ) {
            kq_n = make_float2(kb[(size_t)(t + 1) * KEY_DIM + tid],
                               qb[(size_t)(t + 1) * KEY_DIM + tid]);
            vv_n = vb[(size_t)(t + 1) * CONV_DIM];
            gg_n = g_g[(t + 1) * HVN + hv];
            bb_n = g_beta[(t + 1) * HVN + hv];
        }

        const float eg = expf(gg);
        const float2* kqrow = &skq[buf][r * 33];

        float k0 = 0.f, k1 = 0.f, k2 = 0.f, k3 = 0.f;
#pragma unroll
        for (int i = 0; i < 32; i += 4) {
            S[i + 0] *= eg; k0 = fmaf(kqrow[i + 0].x, S[i + 0], k0);
            S[i + 1] *= eg; k1 = fmaf(kqrow[i + 1].x, S[i + 1], k1);
            S[i + 2] *= eg; k2 = fmaf(kqrow[i + 2].x, S[i + 2], k2);
            S[i + 3] *= eg; k3 = fmaf(kqrow[i + 3].x, S[i + 3], k3);
        }
        float ks = (k0 + k1) + (k2 + k3);
        ks += __shfl_xor_sync(0xffffffffu, ks, 1);
        ks += __shfl_xor_sync(0xffffffffu, ks, 2);
        const float delta = (vv - ks) * bb;

        float o0 = 0.f, o1 = 0.f, o2 = 0.f, o3 = 0.f;
#pragma unroll
        for (int i = 0; i < 32; i += 4) {
            float2 a0 = kqrow[i + 0]; S[i + 0] = fmaf(a0.x, delta, S[i + 0]); o0 = fmaf(a0.y, S[i + 0], o0);
            float2 a1 = kqrow[i + 1]; S[i + 1] = fmaf(a1.x, delta, S[i + 1]); o1 = fmaf(a1.y, S[i + 1], o1);
            float2 a2 = kqrow[i + 2]; S[i + 2] = fmaf(a2.x, delta, S[i + 2]); o2 = fmaf(a2.y, S[i + 2], o2);
            float2 a3 = kqrow[i + 3]; S[i + 3] = fmaf(a3.x, delta, S[i + 3]); o3 = fmaf(a3.y, S[i + 3], o3);
        }
        float o = (o0 + o1) + (o2 + o3);
        o += __shfl_xor_sync(0xffffffffu, o, 1);
        o += __shfl_xor_sync(0xffffffffu, o, 2);
        if (r == 0)
            g_core[(size_t)t * VAL_DIM + hv * 128 + col] = o;

        if (t + 1 < LSEQ) {
            skq[buf ^ 1][sidx] = kq_n;
            vv = vv_n; gg = gg_n; bb = bb_n;
        }
        __syncthreads();
    }
}

// ---------------- gated RMSNorm * silu(z), writes fp16 y ----------------------
__global__ __launch_bounds__(128) void gated_norm_kernel(const float* __restrict__ norm_w)
{
    const int t  = blockIdx.x;
    const int hv = blockIdx.y;
    const int d  = threadIdx.x;
    const int hk = hv >> 1;
    const int gi = hv & 1;

    const float c = g_core[(size_t)t * VAL_DIM + hv * 128 + d];

    __shared__ float s4[4];
    const float ss = block128_sum(c * c, s4, d);
    const float var = ss * (1.f / 128.f);

    const float z  = g_proj[(size_t)t * NPROJ + hk * 768 + 512 + gi * 128 + d];
    const float sz = z / (1.f + expf(-z));

    const float yv = c * (1.f / sqrtf(var + EPSF)) * norm_w[d] * sz;
    g_y_h[(size_t)t * VAL_DIM + hv * 128 + d] = __float2half(yv);
}

// ---------------- launch ------------------------------------------------------
extern "C" void kernel_launch(void* const* d_in, const int* in_sizes, int n_in,
                              void* d_out, int out_size)
{
    const float* hs      = (const float*)d_in[0];
    const float* w_in    = (const float*)d_in[1];
    const float* conv_w  = (const float*)d_in[2];
    const float* A_log   = (const float*)d_in[3];
    const float* dt_bias = (const float*)d_in[4];
    const float* norm_w  = (const float*)d_in[5];
    const float* w_out   = (const float*)d_in[6];
    float* out = (float*)d_out;

    static bool attr_set = false;
    if (!attr_set) {
        cudaFuncSetAttribute(hgemm1,
                             cudaFuncAttributeMaxDynamicSharedMemorySize, GEMM1P_SMEM);
        attr_set = true;
    }

    float *proj_p = nullptr;
    __half *hs_h, *win_h, *wout_h, *y_h;
    cudaGetSymbolAddress((void**)&proj_p, g_proj);
    cudaGetSymbolAddress((void**)&hs_h,   g_hs_h);
    cudaGetSymbolAddress((void**)&win_h,  g_win_h);
    cudaGetSymbolAddress((void**)&wout_h, g_wout_h);
    cudaGetSymbolAddress((void**)&y_h,    g_y_h);

    // 0. convert activations and weights to fp16
    {
        int n4 = LSEQ * HDIM / 4;
        cvt16_kernel<<<(n4 + 255) / 256, 256>>>((const float4*)hs, hs_h, n4);
        n4 = HDIM * NPROJ / 4;
        cvt16_kernel<<<(n4 + 255) / 256, 256>>>((const float4*)w_in, win_h, n4);
        n4 = VAL_DIM * HDIM / 4;
        cvt16_kernel<<<(n4 + 255) / 256, 256>>>((const float4*)w_out, wout_h, n4);
    }

    // 1. in_proj GEMM (1-pass fp16): (4096,2048)@(2048,12352)
    hgemm1<<<dim3((NPROJ + BN - 1) / BN, LSEQ / BM), 256, GEMM1P_SMEM>>>(
        hs_h, win_h, proj_p, LSEQ, NPROJ, HDIM);

    // 2. fused conv+silu+l2norm for q/k; conv+silu for v
    conv_qk_kernel<<<dim3(LSEQ, 32), 128>>>(conv_w);
    conv_v_kernel<<<(LSEQ * VAL_DIM / 4 + 255) / 256, 256>>>(conv_w);

    // 3. beta / g
    gb_kernel<<<(LSEQ * HVN + 255) / 256, 256>>>(A_log, dt_bias);

    // 4. recurrence
    scan_kernel2<<<HVN * 4, 128>>>();

    // 5. gated rmsnorm * silu(z) -> fp16 y
    gated_norm_kernel<<<dim3(LSEQ, HVN), 128>>>(norm_w);

    // 6. out_proj GEMM (1-pass fp16): (4096,4096)@(4096,2048)
    hgemm1<<<dim3(HDIM / BN, LSEQ / BM), 256, GEMM1P_SMEM>>>(
        y_h, wout_h, out, LSEQ, HDIM, VAL_DIM);
}